// round 3
// baseline (speedup 1.0000x reference)
#include <cuda_runtime.h>
#include <math.h>

// Problem shape (fixed per reference): h is (32, 4096, 1024) fp32.
#define BATCH   32
#define SEQ     4096
#define HID     1024
#define W       32          // window rows
#define WSTART  2032        // 4096/2 - 16
#define NCH     8           // d-chunks
#define CHUNK   128         // HID / NCH
#define NPAIR   528         // 32*33/2 upper-triangle incl diag
#define SWEEPS  8

// Scratch: per-batch, per-chunk partial Gram (upper triangle), fp32.
__device__ float g_part[BATCH][NCH][NPAIR];

// ---------------------------------------------------------------------------
// Kernel 1: partial raw Gram R = W W^T over a 128-column chunk.
// grid = (NCH, BATCH), block = 544 (17 warps; 528 pair threads).
// ---------------------------------------------------------------------------
__global__ void __launch_bounds__(544) gram_kernel(const float* __restrict__ h) {
    const int chunk = blockIdx.x;
    const int b     = blockIdx.y;
    __shared__ float As[W][CHUNK + 1];   // pad -> conflict-free column reads

    const int tid = threadIdx.x;
    const float* base = h + ((size_t)b * SEQ + WSTART) * HID + (size_t)chunk * CHUNK;

    // Stage tile: 32 rows x 128 cols = 1024 float4 loads.
    for (int idx = tid; idx < W * (CHUNK / 4); idx += blockDim.x) {
        int row = idx >> 5;           // /32 float4 per row
        int c4  = idx & 31;
        float4 v = *(const float4*)(base + (size_t)row * HID + c4 * 4);
        As[row][c4 * 4 + 0] = v.x;
        As[row][c4 * 4 + 1] = v.y;
        As[row][c4 * 4 + 2] = v.z;
        As[row][c4 * 4 + 3] = v.w;
    }
    __syncthreads();

    if (tid < NPAIR) {
        // decode upper-triangle pair (i, j), i <= j
        int i = 0, rem = tid;
        while (rem >= W - i) { rem -= W - i; i++; }
        int j = i + rem;

        const float* ai = As[i];
        const float* aj = As[j];
        float acc = 0.f;
        #pragma unroll 8
        for (int d = 0; d < CHUNK; d++) acc = fmaf(ai[d], aj[d], acc);
        g_part[b][chunk][tid] = acc;
    }
}

// ---------------------------------------------------------------------------
// Kernel 2: per-batch — reduce partials (fp64), center+normalize to C (fp32),
// parallel Jacobi eigensolve, rank diagonal, emit scores.
// grid = BATCH, block = 1024.
// ---------------------------------------------------------------------------
__global__ void __launch_bounds__(1024) eig_kernel(float* __restrict__ out, int n) {
    const int b   = blockIdx.x;
    const int tid = threadIdx.x;

    __shared__ double Gs[W][W + 1];
    __shared__ double rsum[W];
    __shared__ double Ssum;
    __shared__ double traceSh;
    __shared__ float  dinv[W];
    __shared__ float  Abuf[2][W][W + 1];
    __shared__ float  aco[W], bco[W];
    __shared__ int    part[W];
    __shared__ float  lam[W];
    __shared__ float  evals[3];   // e0, e7, e8

    // --- reduce chunk partials in double, mirror to full symmetric matrix ---
    if (tid < NPAIR) {
        double g = 0.0;
        #pragma unroll
        for (int c = 0; c < NCH; c++) g += (double)g_part[b][c][tid];
        int i = 0, rem = tid;
        while (rem >= W - i) { rem -= W - i; i++; }
        int j = i + rem;
        Gs[i][j] = g;
        Gs[j][i] = g;
    }
    __syncthreads();

    // --- row sums and grand sum (centering terms) ---
    if (tid < W) {
        double r = 0.0;
        #pragma unroll
        for (int j = 0; j < W; j++) r += Gs[tid][j];
        rsum[tid] = r;
    }
    __syncthreads();
    if (tid == 0) {
        double s = 0.0;
        #pragma unroll
        for (int i = 0; i < W; i++) s += rsum[i];
        Ssum = s;
    }
    __syncthreads();

    const double Sq = Ssum * (1.0 / 1024.0);   // S / 32^2

    // --- inverse (norm + eps) per row; centered diag = R_ii - r_i/16 + S/1024 ---
    if (tid < W) {
        double di = Gs[tid][tid] - rsum[tid] * (1.0 / 16.0) + Sq;
        if (di < 0.0) di = 0.0;
        dinv[tid] = (float)(1.0 / (sqrt(di) + 1e-8));
    }
    __syncthreads();

    // --- build normalized covariance C in fp32 ---
    {
        int k = tid >> 5, l = tid & 31;
        double gc = Gs[k][l] - rsum[k] * (1.0 / 32.0) - rsum[l] * (1.0 / 32.0) + Sq;
        Abuf[0][k][l] = (float)gc * dinv[k] * dinv[l];
    }
    __syncthreads();
    if (tid == 0) {
        double tr = 0.0;
        #pragma unroll
        for (int i = 0; i < W; i++) tr += (double)Abuf[0][i][i];
        traceSh = tr;
    }

    // --- parallel cyclic Jacobi: 16 disjoint rotations per round ---
    // Tournament (circle method): round r pairs (31, r) and
    // {(r+m)%31, (r-m)%31} for m=1..15. One warp computes per-row coeffs.
    int cur = 0;
    const int k = tid >> 5, l = tid & 31;
    for (int sw = 0; sw < SWEEPS; sw++) {
        for (int r = 0; r < 31; r++) {
            if (tid < 32) {
                // Thread tid owns row index p = tid; find its partner q.
                int p = tid, q;
                if (p == 31) q = r;
                else {
                    // p = (r+m)%31 -> partner (r-m+31)%31 ; m = (p-r) mod 31
                    int m = p - r; if (m < 0) m += 31;
                    if (m == 0) q = 31;
                    else { q = r - m; if (q < 0) q += 31; }
                }
                // Rotation that zeroes A[p][q]; orientation fixed by (lo,hi).
                int lo = p < q ? p : q;
                int hi = p < q ? q : p;
                float app = Abuf[cur][lo][lo];
                float aqq = Abuf[cur][hi][hi];
                float apq = Abuf[cur][lo][hi];
                float c, s;
                if (fabsf(apq) > 1e-12f) {
                    float tau = __fdividef((aqq - app) * 0.5f, apq);
                    float tt  = __fdividef(1.0f, fabsf(tau) + sqrtf(fmaf(tau, tau, 1.0f)));
                    tt = copysignf(tt, tau);
                    c = rsqrtf(fmaf(tt, tt, 1.0f));
                    s = tt * c;
                } else {
                    c = 1.0f; s = 0.0f;
                }
                // J[lo][lo]=c, J[lo][hi]=-s(?); consistent with prior rounds:
                // row lo gets (c, -s), row hi gets (c, s).
                aco[p] = c;
                bco[p] = (p == lo) ? -s : s;
                part[p] = q;
            }
            __syncthreads();
            {
                int pk = part[k], pl = part[l];
                float ak = aco[k], bk = bco[k];
                float al = aco[l], bl = bco[l];
                float t1 = fmaf(ak, Abuf[cur][k][l],  bk * Abuf[cur][pk][l]);
                float t2 = fmaf(ak, Abuf[cur][k][pl], bk * Abuf[cur][pk][pl]);
                Abuf[cur ^ 1][k][l] = fmaf(al, t1, bl * t2);
            }
            __syncthreads();
            cur ^= 1;
        }
    }

    // --- extract diagonal (eigenvalues) and rank to get e0, e7, e8 ---
    if (tid < W) lam[tid] = Abuf[cur][tid][tid];
    __syncthreads();
    if (tid < W) {
        float v = lam[tid];
        int rank = 0;
        #pragma unroll
        for (int u = 0; u < W; u++) {
            float vu = lam[u];
            if (vu > v || (vu == v && u < tid)) rank++;
        }
        if (rank == 0) evals[0] = v;
        if (rank == 7) evals[1] = v;
        if (rank == 8) evals[2] = v;
    }
    __syncthreads();

    if (tid == 0) {
        float e0 = evals[0], e7 = evals[1], e8 = evals[2];
        float gap   = e7 - e8;
        float decay = (e0 - e8) * (1.0f / 9.0f);
        float lmin  = e8 + 1e-8f;
        float topo  = gap / (decay + 1e-8f);
        if (topo < 0.f) topo = 0.f;
        float geo   = lmin / ((float)traceSh + 1e-8f);
        float gcve  = topo + geo;
        out[b]         = gcve;   // gcve_scores
        out[n + b]     = 0.0f;   // fracture_scores
        out[2 * n + b] = gcve;   // total_pressure
    }
}

// ---------------------------------------------------------------------------
extern "C" void kernel_launch(void* const* d_in, const int* in_sizes, int n_in,
                              void* d_out, int out_size) {
    const float* h = (const float*)d_in[0];
    float* out = (float*)d_out;
    int n = out_size / 3;   // 32

    dim3 g1(NCH, BATCH);
    gram_kernel<<<g1, 544>>>(h);
    eig_kernel<<<BATCH, 1024>>>(out, n);
}

// round 4
// speedup vs baseline: 1.3377x; 1.3377x over previous
#include <cuda_runtime.h>
#include <math.h>

// Problem shape (fixed per reference): h is (32, 4096, 1024) fp32.
#define BATCH   32
#define SEQ     4096
#define HID     1024
#define W       32          // window rows
#define WSTART  2032        // 4096/2 - 16
#define NCH     8           // d-chunks
#define CHUNK   128         // HID / NCH
#define NPAIR   528         // 32*33/2 upper-triangle incl diag
#define SWEEPS  6

// Scratch: per-batch, per-chunk partial Gram (upper triangle), fp32.
__device__ float g_part[BATCH][NCH][NPAIR];

// ---------------------------------------------------------------------------
// Kernel 1: partial raw Gram R = W W^T over a 128-column chunk.
// grid = (NCH, BATCH), block = 544 (17 warps; 528 pair threads).
// ---------------------------------------------------------------------------
__global__ void __launch_bounds__(544) gram_kernel(const float* __restrict__ h) {
    const int chunk = blockIdx.x;
    const int b     = blockIdx.y;
    __shared__ float As[W][CHUNK + 1];   // pad -> conflict-free column reads

    const int tid = threadIdx.x;
    const float* base = h + ((size_t)b * SEQ + WSTART) * HID + (size_t)chunk * CHUNK;

    // Stage tile: 32 rows x 128 cols = 1024 float4 loads.
    for (int idx = tid; idx < W * (CHUNK / 4); idx += blockDim.x) {
        int row = idx >> 5;           // /32 float4 per row
        int c4  = idx & 31;
        float4 v = *(const float4*)(base + (size_t)row * HID + c4 * 4);
        As[row][c4 * 4 + 0] = v.x;
        As[row][c4 * 4 + 1] = v.y;
        As[row][c4 * 4 + 2] = v.z;
        As[row][c4 * 4 + 3] = v.w;
    }
    __syncthreads();

    if (tid < NPAIR) {
        // decode upper-triangle pair (i, j), i <= j
        int i = 0, rem = tid;
        while (rem >= W - i) { rem -= W - i; i++; }
        int j = i + rem;

        const float* ai = As[i];
        const float* aj = As[j];
        float acc = 0.f;
        #pragma unroll 8
        for (int d = 0; d < CHUNK; d++) acc = fmaf(ai[d], aj[d], acc);
        g_part[b][chunk][tid] = acc;
    }
}

// ---------------------------------------------------------------------------
// Kernel 2: per-batch — reduce partials (fp64), center+normalize to C (fp32),
// parallel Jacobi eigensolve, rank diagonal, emit scores.
// grid = BATCH, block = 256 (8 warps). One barrier per Jacobi round.
// ---------------------------------------------------------------------------
__global__ void __launch_bounds__(256) eig_kernel(float* __restrict__ out, int n) {
    const int b    = blockIdx.x;
    const int tid  = threadIdx.x;
    const int lane = tid & 31;
    const int wid  = tid >> 5;

    __shared__ double Gs[W][W + 1];
    __shared__ double rsum[W];
    __shared__ double Ssum;
    __shared__ double traceSh;
    __shared__ float  dinv[W];
    __shared__ float  Abuf[2][W][W + 1];
    __shared__ float  lam[W];
    __shared__ float  evals[3];   // e0, e7, e8

    // --- reduce chunk partials in double, mirror to full symmetric matrix ---
    for (int t = tid; t < NPAIR; t += 256) {
        double g = 0.0;
        #pragma unroll
        for (int c = 0; c < NCH; c++) g += (double)g_part[b][c][t];
        int i = 0, rem = t;
        while (rem >= W - i) { rem -= W - i; i++; }
        int j = i + rem;
        Gs[i][j] = g;
        Gs[j][i] = g;
    }
    __syncthreads();

    // --- row sums and grand sum (centering terms) ---
    if (tid < W) {
        double r = 0.0;
        #pragma unroll
        for (int j = 0; j < W; j++) r += Gs[tid][j];
        rsum[tid] = r;
    }
    __syncthreads();
    if (tid == 0) {
        double s = 0.0;
        #pragma unroll
        for (int i = 0; i < W; i++) s += rsum[i];
        Ssum = s;
    }
    __syncthreads();

    const double Sq = Ssum * (1.0 / 1024.0);   // S / 32^2

    // --- inverse (norm + eps) per row; centered diag = R_ii - r_i/16 + S/1024 ---
    if (tid < W) {
        double di = Gs[tid][tid] - rsum[tid] * (1.0 / 16.0) + Sq;
        if (di < 0.0) di = 0.0;
        dinv[tid] = (float)(1.0 / (sqrt(di) + 1e-8));
    }
    __syncthreads();

    // --- build normalized covariance C in fp32 (4 elements per thread) ---
    {
        #pragma unroll
        for (int e = 0; e < 4; e++) {
            int idx = tid + e * 256;
            int k = idx >> 5, l = idx & 31;
            double gc = Gs[k][l] - rsum[k] * (1.0 / 32.0) - rsum[l] * (1.0 / 32.0) + Sq;
            Abuf[0][k][l] = (float)gc * dinv[k] * dinv[l];
        }
    }
    __syncthreads();
    if (tid == 0) {
        double tr = 0.0;
        #pragma unroll
        for (int i = 0; i < W; i++) tr += (double)Abuf[0][i][i];
        traceSh = tr;
    }

    // --- parallel cyclic Jacobi: 16 disjoint rotations per round ---
    // Tournament (circle method): round r pairs (31, r) and
    // {(r+m)%31, (r-m)%31} for m=1..15.
    // Every warp redundantly computes all 32 per-row rotation coeffs in
    // registers (lane p -> row p); update pulls them with uniform shfl.
    // One __syncthreads per round.
    int cur = 0;
    const int k0 = wid * 4;     // this thread's 4 rows
    const int l  = lane;        // this thread's column
    for (int sw = 0; sw < SWEEPS; sw++) {
        for (int r = 0; r < 31; r++) {
            // -- per-lane rotation coefficients for row p = lane --
            int p = lane, q;
            if (p == 31) q = r;
            else {
                int m = p - r; if (m < 0) m += 31;
                if (m == 0) q = 31;
                else { q = r - m; if (q < 0) q += 31; }
            }
            int lo = p < q ? p : q;
            int hi = p < q ? q : p;
            float app = Abuf[cur][lo][lo];
            float aqq = Abuf[cur][hi][hi];
            float apq = Abuf[cur][lo][hi];
            float my_a, my_b;
            if (fabsf(apq) > 1e-12f) {
                float tau = __fdividef((aqq - app) * 0.5f, apq);
                float tt  = __fdividef(1.0f, fabsf(tau) + sqrtf(fmaf(tau, tau, 1.0f)));
                tt = copysignf(tt, tau);
                float c = rsqrtf(fmaf(tt, tt, 1.0f));
                float s = tt * c;
                my_a = c;
                my_b = (p == lo) ? -s : s;
            } else {
                my_a = 1.0f; my_b = 0.0f;
            }
            int my_part = q;

            // -- column coeffs: this lane's own registers --
            const float al = my_a, bl = my_b;
            const int   pl = my_part;

            // -- update 4 rows of column l --
            float nv[4];
            #pragma unroll
            for (int kk = 0; kk < 4; kk++) {
                int k = k0 + kk;
                float ak = __shfl_sync(0xFFFFFFFFu, my_a, k);
                float bk = __shfl_sync(0xFFFFFFFFu, my_b, k);
                int   pk = __shfl_sync(0xFFFFFFFFu, my_part, k);
                float t1 = fmaf(ak, Abuf[cur][k][l],  bk * Abuf[cur][pk][l]);
                float t2 = fmaf(ak, Abuf[cur][k][pl], bk * Abuf[cur][pk][pl]);
                nv[kk] = fmaf(al, t1, bl * t2);
            }
            #pragma unroll
            for (int kk = 0; kk < 4; kk++)
                Abuf[cur ^ 1][k0 + kk][l] = nv[kk];

            __syncthreads();
            cur ^= 1;
        }
    }

    // --- extract diagonal (eigenvalues) and rank to get e0, e7, e8 ---
    if (tid < W) lam[tid] = Abuf[cur][tid][tid];
    __syncthreads();
    if (tid < W) {
        float v = lam[tid];
        int rank = 0;
        #pragma unroll
        for (int u = 0; u < W; u++) {
            float vu = lam[u];
            if (vu > v || (vu == v && u < tid)) rank++;
        }
        if (rank == 0) evals[0] = v;
        if (rank == 7) evals[1] = v;
        if (rank == 8) evals[2] = v;
    }
    __syncthreads();

    if (tid == 0) {
        float e0 = evals[0], e7 = evals[1], e8 = evals[2];
        float gap   = e7 - e8;
        float decay = (e0 - e8) * (1.0f / 9.0f);
        float lmin  = e8 + 1e-8f;
        float topo  = gap / (decay + 1e-8f);
        if (topo < 0.f) topo = 0.f;
        float geo   = lmin / ((float)traceSh + 1e-8f);
        float gcve  = topo + geo;
        out[b]         = gcve;   // gcve_scores
        out[n + b]     = 0.0f;   // fracture_scores
        out[2 * n + b] = gcve;   // total_pressure
    }
}

// ---------------------------------------------------------------------------
extern "C" void kernel_launch(void* const* d_in, const int* in_sizes, int n_in,
                              void* d_out, int out_size) {
    const float* h = (const float*)d_in[0];
    float* out = (float*)d_out;
    int n = out_size / 3;   // 32

    dim3 g1(NCH, BATCH);
    gram_kernel<<<g1, 544>>>(h);
    eig_kernel<<<BATCH, 256>>>(out, n);
}